// round 2
// baseline (speedup 1.0000x reference)
#include <cuda_runtime.h>
#include <cstdint>

#define Bsz 1024
#define Tt 64
#define Dd 128
#define Hh 128
#define ATT 64
#define HOR 24
#define G 8
#define NCTAS (Bsz/G)
#define NTHR 512

// ---------------- device scratch (no allocations allowed) ----------------
__device__ float g_WihT[Dd * 4 * Hh];   // [k][o] 128 x 512 (enc_Wih transposed)
__device__ float g_WhhT[Hh * 4 * Hh];   // [k][o] 128 x 512 (enc_Whh transposed)
__device__ float g_WhhTd[Hh * 4 * Hh];  // [k][o] 128 x 512 (dec_Whh transposed)
__device__ float g_hid[(size_t)Bsz * Tt * Hh];   // encoder hiddens [b][t][h]
__device__ float g_proj[(size_t)Bsz * ATT * Tt]; // enc_proj transposed [b][a][t]

// ---------------- helpers ----------------
__device__ __forceinline__ float tanh_fast(float x) {
    float y; asm("tanh.approx.f32 %0, %1;" : "=f"(y) : "f"(x)); return y;
}
__device__ __forceinline__ float sigm(float x) {
    return 1.f / (1.f + __expf(-x));
}
__device__ __forceinline__ float tanh_acc(float x) {
    float ax = fabsf(x);
    float e = __expf(-2.f * ax);
    float t = (1.f - e) / (1.f + e);
    return copysignf(t, x);
}

// ---------------- prologue: transpose LSTM weight matrices ----------------
__global__ void transpose_k(const float* __restrict__ Wih,
                            const float* __restrict__ Whh,
                            const float* __restrict__ Wdh) {
    int i = blockIdx.x * blockDim.x + threadIdx.x;
    if (i < 512 * 128) {
        int o = i >> 7, k = i & 127;    // source row-major (512,128)
        g_WihT[k * 512 + o]  = Wih[i];
        g_WhhT[k * 512 + o]  = Whh[i];
        g_WhhTd[k * 512 + o] = Wdh[i];
    }
}

// smem float counts
#define OFF_W      0
#define SZ_W       24640              // 64*385 (holds We_w@257 or Wd_w@385)
#define OFF_H      (OFF_W + SZ_W)
#define OFF_C      (OFF_H + 1024)
#define OFF_X      (OFF_C + 1024)
#define OFF_BASE   (OFF_X + 1024)
#define OFF_SC     (OFF_BASE + 512)
#define OFF_GATES  (OFF_SC + 1024)
#define OFF_BIAS   (OFF_GATES + 4096)
#define OFF_WEB    (OFF_BIAS + 512)
#define OFF_VEW    (OFF_WEB + 64)
#define OFF_WDB    (OFF_VEW + 64)
#define OFF_VDW    (OFF_WDB + 64)
#define OFF_DWIH   (OFF_VDW + 64)
#define OFF_FCW    (OFF_DWIH + 512)
#define OFF_YH     (OFF_FCW + 320)
#define OFF_RED    (OFF_YH + 512)
#define OFF_RED2   (OFF_RED + 16)
#define OFF_YPREV  (OFF_RED2 + 16)
#define SMEM_FLOATS (OFF_YPREV + 8)
#define SMEM_BYTES  (SMEM_FLOATS * 4)

__global__ void __launch_bounds__(NTHR, 1)
darnn_kernel(const float* __restrict__ X,        const float* __restrict__ y_hist,
             const float* __restrict__ We_w,     const float* __restrict__ We_b,
             const float* __restrict__ ve_w,     const float* __restrict__ ve_b,
             const float* __restrict__ enc_bih,  const float* __restrict__ enc_bhh,
             const float* __restrict__ dec_Wih,  const float* __restrict__ dec_bih,
             const float* __restrict__ dec_bhh,
             const float* __restrict__ Wd_w,     const float* __restrict__ Wd_b,
             const float* __restrict__ vd_w,     const float* __restrict__ vd_b,
             const float* __restrict__ fc_w,     const float* __restrict__ fc_b,
             float* __restrict__ out) {
    extern __shared__ float sm[];
    float* sW      = sm + OFF_W;
    float* s_h     = sm + OFF_H;
    float* s_c     = sm + OFF_C;
    float* s_x     = sm + OFF_X;      // x_t / x_tilde / hid-stage / context
    float* s_base  = sm + OFF_BASE;
    float* s_sc    = sm + OFF_SC;     // beta in decoder
    float* s_gates = sm + OFF_GATES;
    float* s_bias  = sm + OFF_BIAS;
    float* s_Web   = sm + OFF_WEB;
    float* s_vew   = sm + OFF_VEW;
    float* s_Wdb   = sm + OFF_WDB;
    float* s_vdw   = sm + OFF_VDW;
    float* s_dWih  = sm + OFF_DWIH;
    float* s_fcw   = sm + OFF_FCW;
    float* s_yh    = sm + OFF_YH;
    float* s_red   = sm + OFF_RED;
    float* s_red2  = sm + OFF_RED2;
    float* s_yprev = sm + OFF_YPREV;

    const int tid  = threadIdx.x;
    const int lane = tid & 31;
    const int wrp  = tid >> 5;
    const int b0   = blockIdx.x * G;

    const float ve_b_r = ve_b[0];

    // ---------- preload (encoder) ----------
    for (int i = tid; i < 64 * 257; i += NTHR) sW[i] = We_w[i];   // stride 257 kept
    if (tid < 512) s_bias[tid] = enc_bih[tid] + enc_bhh[tid];
    if (tid < 64) { s_Web[tid] = We_b[tid]; s_vew[tid] = ve_w[tid]; }
    if (tid < G * Tt) s_yh[tid] = y_hist[b0 * Tt + tid];
    if (tid < G * Hh) { s_h[tid] = 0.f; s_c[tid] = 0.f; }
    if (tid + NTHR < G * Hh) { s_h[tid + NTHR] = 0.f; s_c[tid + NTHR] = 0.f; }
    __syncthreads();

    const float4* WihT4  = reinterpret_cast<const float4*>(g_WihT);
    const float4* WhhT4  = reinterpret_cast<const float4*>(g_WhhT);
    const float4* WhhTd4 = reinterpret_cast<const float4*>(g_WhhTd);
    float4* s_gates4 = reinterpret_cast<float4*>(s_gates);

    // ================= ENCODER: 64 steps =================
    for (int t = 0; t < Tt; ++t) {
        // E1: load x_t into smem [g][d]
        {
            const float* Xp = X + (size_t)b0 * Tt * Dd + (size_t)t * Dd;
            int i = tid;
            s_x[i] = Xp[(i >> 7) * Tt * Dd + (i & 127)];
            i = tid + NTHR;
            s_x[i] = Xp[(i >> 7) * Tt * Dd + (i & 127)];
        }
        // E2: base[g][a] = We_b[a] + h·Whs[a,:128] + c·Whs[a,128:256]
        {
            int g = tid >> 6, a = tid & 63;
            const float* Wr = sW + a * 257;
            const float* hg = s_h + g * 128;
            const float* cg = s_c + g * 128;
            float acc = s_Web[a];
            #pragma unroll 8
            for (int j = 0; j < 128; ++j) acc = fmaf(hg[j], Wr[j], acc);
            #pragma unroll 8
            for (int j = 0; j < 128; ++j) acc = fmaf(cg[j], Wr[128 + j], acc);
            s_base[tid] = acc;
        }
        __syncthreads();
        // E3+E4: scores, softmax over D, x_tilde (in place)
        {
            int g = tid >> 6, d0 = tid & 63;
            float x1 = s_x[g * 128 + d0];
            float x2 = s_x[g * 128 + d0 + 64];
            float a1 = ve_b_r, a2 = ve_b_r;
            const float* bg = s_base + g * 64;
            #pragma unroll 4
            for (int a = 0; a < 64; ++a) {
                float ba = bg[a];
                float wf = sW[a * 257 + 256];
                float vw = s_vew[a];
                a1 = fmaf(vw, tanh_fast(fmaf(x1, wf, ba)), a1);
                a2 = fmaf(vw, tanh_fast(fmaf(x2, wf, ba)), a2);
            }
            float m = fmaxf(a1, a2);
            #pragma unroll
            for (int o = 16; o; o >>= 1) m = fmaxf(m, __shfl_xor_sync(0xffffffffu, m, o));
            if (lane == 0) s_red[wrp] = m;
            __syncthreads();
            float gm = fmaxf(s_red[2 * g], s_red[2 * g + 1]);
            float e1 = __expf(a1 - gm), e2 = __expf(a2 - gm);
            float ss = e1 + e2;
            #pragma unroll
            for (int o = 16; o; o >>= 1) ss += __shfl_xor_sync(0xffffffffu, ss, o);
            if (lane == 0) s_red2[wrp] = ss;
            __syncthreads();
            float inv = 1.f / (s_red2[2 * g] + s_red2[2 * g + 1]);
            s_x[g * 128 + d0]      = x1 * e1 * inv;
            s_x[g * 128 + d0 + 64] = x2 * e2 * inv;
        }
        __syncthreads();
        // E5: gates[g][o] = bias + x_tilde·Wih^T + h·Whh^T
        {
            int gg = tid >> 7, og = tid & 127;
            int g0 = gg * 2, g1 = g0 + 1;
            int o0 = og * 4;
            float a00 = s_bias[o0 + 0], a10 = s_bias[o0 + 1];
            float a20 = s_bias[o0 + 2], a30 = s_bias[o0 + 3];
            float a01 = a00, a11 = a10, a21 = a20, a31 = a30;
            const float* xa = s_x + g0 * 128;
            const float* xb = s_x + g1 * 128;
            const float* ha = s_h + g0 * 128;
            const float* hb = s_h + g1 * 128;
            #pragma unroll 4
            for (int k = 0; k < 128; ++k) {
                float4 w = __ldg(&WihT4[k * 128 + og]);
                float va = xa[k], vb = xb[k];
                a00 = fmaf(w.x, va, a00); a01 = fmaf(w.x, vb, a01);
                a10 = fmaf(w.y, va, a10); a11 = fmaf(w.y, vb, a11);
                a20 = fmaf(w.z, va, a20); a21 = fmaf(w.z, vb, a21);
                a30 = fmaf(w.w, va, a30); a31 = fmaf(w.w, vb, a31);
            }
            #pragma unroll 4
            for (int k = 0; k < 128; ++k) {
                float4 w = __ldg(&WhhT4[k * 128 + og]);
                float va = ha[k], vb = hb[k];
                a00 = fmaf(w.x, va, a00); a01 = fmaf(w.x, vb, a01);
                a10 = fmaf(w.y, va, a10); a11 = fmaf(w.y, vb, a11);
                a20 = fmaf(w.z, va, a20); a21 = fmaf(w.z, vb, a21);
                a30 = fmaf(w.w, va, a30); a31 = fmaf(w.w, vb, a31);
            }
            s_gates4[g0 * 128 + og] = make_float4(a00, a10, a20, a30);
            s_gates4[g1 * 128 + og] = make_float4(a01, a11, a21, a31);
        }
        __syncthreads();
        // E6: LSTM cell update, store h2 to global hiddens
        {
            int u = tid & 127, gb = tid >> 7;
            #pragma unroll
            for (int q = 0; q < 2; ++q) {
                int g = gb + q * 4;
                const float* gr = s_gates + g * 512;
                float ig = sigm(gr[u]);
                float fg = sigm(gr[128 + u]);
                float gv = tanh_acc(gr[256 + u]);
                float ov = sigm(gr[384 + u]);
                float c2 = fmaf(fg, s_c[g * 128 + u], ig * gv);
                float h2 = ov * tanh_acc(c2);
                s_c[g * 128 + u] = c2;
                s_h[g * 128 + u] = h2;
                g_hid[((size_t)(b0 + g)) * Tt * Hh + (size_t)t * Hh + u] = h2;
            }
        }
        __syncthreads();
    }

    // ================= enc_proj: proj[b][a][t] = hid[b][t][:]·Wd_w[a,:128] =================
    for (int i = tid; i < 64 * 384; i += NTHR) {
        int r = i / 384, cc = i - r * 384;
        sW[r * 385 + cc] = Wd_w[i];
    }
    __syncthreads();
    for (int t = 0; t < Tt; ++t) {
        {
            const float* hp = g_hid + (size_t)b0 * Tt * Hh + (size_t)t * Hh;
            int i = tid;
            s_x[i] = hp[(i >> 7) * Tt * Hh + (i & 127)];
            i = tid + NTHR;
            s_x[i] = hp[(i >> 7) * Tt * Hh + (i & 127)];
        }
        __syncthreads();
        {
            int g = tid >> 6, a = tid & 63;
            const float* Wr = sW + a * 385;
            const float* hg = s_x + g * 128;
            float acc = 0.f;
            #pragma unroll 8
            for (int j = 0; j < 128; ++j) acc = fmaf(hg[j], Wr[j], acc);
            g_proj[((size_t)(b0 + g)) * ATT * Tt + a * Tt + t] = acc;
        }
        __syncthreads();
    }

    // ---------- preload (decoder) ----------
    if (tid < 512) {
        s_bias[tid] = dec_bih[tid] + dec_bhh[tid];
        s_dWih[tid] = dec_Wih[tid];
    }
    if (tid < 64) { s_Wdb[tid] = Wd_b[tid]; s_vdw[tid] = vd_w[tid]; }
    if (tid < 320) s_fcw[tid] = fc_w[tid];
    if (tid < G * Hh) { s_h[tid] = 0.f; s_c[tid] = 0.f; }
    if (tid + NTHR < G * Hh) { s_h[tid + NTHR] = 0.f; s_c[tid + NTHR] = 0.f; }
    if (tid < G) s_yprev[tid] = s_yh[tid * Tt + Tt - 1];
    const float vd_b_r = vd_b[0];
    const float fc_b_r = fc_b[0];
    __syncthreads();

    // ================= DECODER: 24 steps =================
    for (int s = 0; s < HOR; ++s) {
        // D1: dc[g][a]
        {
            int g = tid >> 6, a = tid & 63;
            const float* Wr = sW + a * 385;
            const float* dg = s_h + g * 128;
            const float* cg = s_c + g * 128;
            float acc = s_Wdb[a];
            #pragma unroll 8
            for (int j = 0; j < 128; ++j) acc = fmaf(dg[j], Wr[128 + j], acc);
            #pragma unroll 8
            for (int j = 0; j < 128; ++j) acc = fmaf(cg[j], Wr[256 + j], acc);
            s_base[tid] = acc;
        }
        __syncthreads();
        // D2+D3: temporal scores + softmax -> beta in s_sc
        {
            int g = tid >> 6, tt = tid & 63;
            const float* pp = g_proj + ((size_t)(b0 + g)) * ATT * Tt + tt;
            const float* bg = s_base + g * 64;
            float acc = vd_b_r;
            #pragma unroll 4
            for (int a = 0; a < 64; ++a)
                acc = fmaf(s_vdw[a], tanh_fast(pp[a * 64] + bg[a]), acc);
            float m = acc;
            #pragma unroll
            for (int o = 16; o; o >>= 1) m = fmaxf(m, __shfl_xor_sync(0xffffffffu, m, o));
            if (lane == 0) s_red[wrp] = m;
            __syncthreads();
            float gm = fmaxf(s_red[2 * g], s_red[2 * g + 1]);
            float e = __expf(acc - gm);
            float ssum = e;
            #pragma unroll
            for (int o = 16; o; o >>= 1) ssum += __shfl_xor_sync(0xffffffffu, ssum, o);
            if (lane == 0) s_red2[wrp] = ssum;
            __syncthreads();
            float inv = 1.f / (s_red2[2 * g] + s_red2[2 * g + 1]);
            s_sc[g * 64 + tt] = e * inv;
        }
        __syncthreads();
        // D4: context[g][u] -> s_x
        {
            int u = tid & 127, gb = tid >> 7;
            #pragma unroll
            for (int q = 0; q < 2; ++q) {
                int g = gb + q * 4;
                const float* hp = g_hid + ((size_t)(b0 + g)) * Tt * Hh + u;
                const float* be = s_sc + g * 64;
                float acc = 0.f;
                #pragma unroll 8
                for (int tt = 0; tt < 64; ++tt) acc = fmaf(be[tt], hp[tt * 128], acc);
                s_x[g * 128 + u] = acc;
            }
        }
        __syncthreads();
        // D5: decoder LSTM gates (input is scalar y_prev)
        {
            int gg = tid >> 7, og = tid & 127;
            int g0 = gg * 2, g1 = g0 + 1;
            int o0 = og * 4;
            float y0 = s_yprev[g0], y1 = s_yprev[g1];
            float a00 = fmaf(s_dWih[o0 + 0], y0, s_bias[o0 + 0]);
            float a10 = fmaf(s_dWih[o0 + 1], y0, s_bias[o0 + 1]);
            float a20 = fmaf(s_dWih[o0 + 2], y0, s_bias[o0 + 2]);
            float a30 = fmaf(s_dWih[o0 + 3], y0, s_bias[o0 + 3]);
            float a01 = fmaf(s_dWih[o0 + 0], y1, s_bias[o0 + 0]);
            float a11 = fmaf(s_dWih[o0 + 1], y1, s_bias[o0 + 1]);
            float a21 = fmaf(s_dWih[o0 + 2], y1, s_bias[o0 + 2]);
            float a31 = fmaf(s_dWih[o0 + 3], y1, s_bias[o0 + 3]);
            const float* ha = s_h + g0 * 128;
            const float* hb = s_h + g1 * 128;
            #pragma unroll 4
            for (int k = 0; k < 128; ++k) {
                float4 w = __ldg(&WhhTd4[k * 128 + og]);
                float va = ha[k], vb = hb[k];
                a00 = fmaf(w.x, va, a00); a01 = fmaf(w.x, vb, a01);
                a10 = fmaf(w.y, va, a10); a11 = fmaf(w.y, vb, a11);
                a20 = fmaf(w.z, va, a20); a21 = fmaf(w.z, vb, a21);
                a30 = fmaf(w.w, va, a30); a31 = fmaf(w.w, vb, a31);
            }
            s_gates4[g0 * 128 + og] = make_float4(a00, a10, a20, a30);
            s_gates4[g1 * 128 + og] = make_float4(a01, a11, a21, a31);
        }
        __syncthreads();
        // D6: LSTM update (d2 in s_h)
        {
            int u = tid & 127, gb = tid >> 7;
            #pragma unroll
            for (int q = 0; q < 2; ++q) {
                int g = gb + q * 4;
                const float* gr = s_gates + g * 512;
                float ig = sigm(gr[u]);
                float fg = sigm(gr[128 + u]);
                float gv = tanh_acc(gr[256 + u]);
                float ov = sigm(gr[384 + u]);
                float c2 = fmaf(fg, s_c[g * 128 + u], ig * gv);
                float h2 = ov * tanh_acc(c2);
                s_c[g * 128 + u] = c2;
                s_h[g * 128 + u] = h2;
            }
        }
        __syncthreads();
        // D7: fc  out = fc_b + fc_w · [d2, context, y_hist]
        if (wrp < G) {
            int g = wrp;
            float acc = 0.f;
            for (int idx = lane; idx < 320; idx += 32) {
                float v;
                if (idx < 128)       v = s_h[g * 128 + idx];
                else if (idx < 256)  v = s_x[g * 128 + idx - 128];
                else                 v = s_yh[g * 64 + idx - 256];
                acc = fmaf(s_fcw[idx], v, acc);
            }
            #pragma unroll
            for (int o = 16; o; o >>= 1) acc += __shfl_xor_sync(0xffffffffu, acc, o);
            if (lane == 0) {
                float ov = acc + fc_b_r;
                s_yprev[g] = ov;
                out[(b0 + g) * HOR + s] = ov;
            }
        }
        __syncthreads();
    }
}

extern "C" void kernel_launch(void* const* d_in, const int* in_sizes, int n_in,
                              void* d_out, int out_size) {
    const float* X        = (const float*)d_in[0];
    const float* y_hist   = (const float*)d_in[1];
    const float* We_w     = (const float*)d_in[2];
    const float* We_b     = (const float*)d_in[3];
    const float* ve_w     = (const float*)d_in[4];
    const float* ve_b     = (const float*)d_in[5];
    const float* enc_Wih  = (const float*)d_in[6];
    const float* enc_Whh  = (const float*)d_in[7];
    const float* enc_bih  = (const float*)d_in[8];
    const float* enc_bhh  = (const float*)d_in[9];
    const float* dec_Wih  = (const float*)d_in[10];
    const float* dec_Whh  = (const float*)d_in[11];
    const float* dec_bih  = (const float*)d_in[12];
    const float* dec_bhh  = (const float*)d_in[13];
    const float* Wd_w     = (const float*)d_in[14];
    const float* Wd_b     = (const float*)d_in[15];
    const float* vd_w     = (const float*)d_in[16];
    const float* vd_b     = (const float*)d_in[17];
    const float* fc_w     = (const float*)d_in[18];
    const float* fc_b     = (const float*)d_in[19];
    float* out = (float*)d_out;

    cudaFuncSetAttribute(darnn_kernel,
                         cudaFuncAttributeMaxDynamicSharedMemorySize, SMEM_BYTES);

    transpose_k<<<(512 * 128 + 255) / 256, 256>>>(enc_Wih, enc_Whh, dec_Whh);
    darnn_kernel<<<NCTAS, NTHR, SMEM_BYTES>>>(
        X, y_hist, We_w, We_b, ve_w, ve_b,
        enc_bih, enc_bhh, dec_Wih, dec_bih, dec_bhh,
        Wd_w, Wd_b, vd_w, vd_b, fc_w, fc_b, out);
}